// round 10
// baseline (speedup 1.0000x reference)
#include <cuda_runtime.h>

// ---------------------------------------------------------------------------
// Problem constants
// ---------------------------------------------------------------------------
#define BATCH   4
#define NPOS    196608          // 256*256*3 positions per batch
#define F       64              // filters
#define NCHUNK  512             // chunks per batch (scan granularity)
#define CS      384             // positions per chunk (multiple of 3)
#define TP      24              // positions staged in smem per tile (8 pixels)
#define FT      24              // final-kernel tile positions
#define SCALE   (1.0f/196608.0f)

typedef unsigned long long ull;

// ---------------------------------------------------------------------------
// Scratch (device globals: allocation-free per harness rules)
// ---------------------------------------------------------------------------
__device__ float g_bufA[(size_t)BATCH * NPOS * F];   // 201 MB
__device__ float g_bufB[(size_t)BATCH * NPOS * F];   // 201 MB
__device__ float g_csum[BATCH * NCHUNK * F];
__device__ float g_off [BATCH * NCHUNK * F];

// ---------------------------------------------------------------------------
// Packed f32x2 helpers (sm_103a packed FMA pipe)
// ---------------------------------------------------------------------------
__device__ __forceinline__ ull pack2(float a, float b) {
    ull r; asm("mov.b64 %0, {%1,%2};" : "=l"(r) : "f"(a), "f"(b)); return r;
}
__device__ __forceinline__ void unpack2(ull v, float& a, float& b) {
    asm("mov.b64 {%0,%1}, %2;" : "=f"(a), "=f"(b) : "l"(v));
}
__device__ __forceinline__ ull ffma2(ull a, ull b, ull c) {
    ull d; asm("fma.rn.f32x2 %0, %1, %2, %3;" : "=l"(d) : "l"(a), "l"(b), "l"(c));
    return d;
}

// ---------------------------------------------------------------------------
// Layer 0: x -> ReLU(w0[c]*x + b0[c]) -> chunk-local cumsum into g_bufA
// One block per (batch, chunk); 64 threads, thread = feature e.
// ---------------------------------------------------------------------------
__global__ __launch_bounds__(64)
void layer0_kernel(const int* __restrict__ ex,
                   const float* __restrict__ W0,   // [3][1][64]
                   const float* __restrict__ b0) { // [3][64]
    int batch = blockIdx.x / NCHUNK;
    int chunk = blockIdx.x % NCHUNK;
    int e = threadIdx.x;
    size_t base = (size_t)batch * NPOS + (size_t)chunk * CS;

    float w[3], bb[3];
#pragma unroll
    for (int c = 0; c < 3; ++c) { w[c] = W0[c * 64 + e]; bb[c] = b0[c * 64 + e]; }

    __shared__ int xs[96];
    float run = 0.0f;
    float* out = g_bufA + base * F;
    const int* exb = ex + base;

    for (int tile = 0; tile < CS / 96; ++tile) {
        __syncthreads();
        xs[threadIdx.x] = exb[tile * 96 + threadIdx.x];
        if (threadIdx.x < 32) xs[threadIdx.x + 64] = exb[tile * 96 + threadIdx.x + 64];
        __syncthreads();
#pragma unroll
        for (int px = 0; px < 32; ++px) {
#pragma unroll
            for (int c = 0; c < 3; ++c) {
                int p = px * 3 + c;
                float xf = (float)xs[p] * 0.25f - 1.0f;   // /8*2-1
                float v = fmaxf(fmaf(w[c], xf, bb[c]), 0.0f);
                run += v;
                out[(size_t)(tile * 96 + p) * F + e] = run;
            }
        }
    }
    g_csum[(batch * NCHUNK + chunk) * F + e] = run;
}

// ---------------------------------------------------------------------------
// Exclusive scan over chunk sums -> per-chunk offsets. One block per batch.
// ---------------------------------------------------------------------------
__global__ __launch_bounds__(64)
void scan_kernel() {
    int b = blockIdx.x;
    int e = threadIdx.x;
    float run = 0.0f;
#pragma unroll 8
    for (int k = 0; k < NCHUNK; ++k) {
        int i = (b * NCHUNK + k) * F + e;
        float t = g_csum[i];
        g_off[i] = run;
        run += t;
    }
}

// ---------------------------------------------------------------------------
// Mid layers 1..3: u = (in + off)*SCALE ; v = ReLU(W[c]^T u + b[c]) ;
// chunk-local cumsum -> out.   128 threads: thread = (feature e, d-half h).
// W columns live in registers (96 regs); u staged in smem, read as LDS.128;
// partner halves combined with shfl_xor(1).
// ---------------------------------------------------------------------------
__global__ __launch_bounds__(128, 3)
void layer_kernel(int src,
                  const float* __restrict__ W,      // [3][64][64] (c,d,e)
                  const float* __restrict__ bias) { // [3][64]
    int batch = blockIdx.x / NCHUNK;
    int chunk = blockIdx.x % NCHUNK;
    int tid = threadIdx.x;
    int lane = tid & 31, wrp = tid >> 5;
    int e = wrp * 16 + (lane >> 1);
    int h = lane & 1;

    const float* in = src ? g_bufB : g_bufA;
    float*       out = src ? g_bufA : g_bufB;
    size_t base = (size_t)batch * NPOS + (size_t)chunk * CS;
    in  += base * F;
    out += base * F;

    // Register-resident weight columns: d in {8j + 4h + 0..3}
    ull wr[3][8][2];
#pragma unroll
    for (int c = 0; c < 3; ++c)
#pragma unroll
        for (int j = 0; j < 8; ++j) {
            int d0 = 8 * j + 4 * h;
            wr[c][j][0] = pack2(W[(c * 64 + d0    ) * 64 + e], W[(c * 64 + d0 + 1) * 64 + e]);
            wr[c][j][1] = pack2(W[(c * 64 + d0 + 2) * 64 + e], W[(c * 64 + d0 + 3) * 64 + e]);
        }
    float bs[3];
#pragma unroll
    for (int c = 0; c < 3; ++c) bs[c] = bias[c * 64 + e];

    float offd = g_off[(batch * NCHUNK + chunk) * F + (tid & 63)];

    __shared__ float us[TP * F];   // 6 KB
    float run = 0.0f;

    for (int tile = 0; tile < CS / TP; ++tile) {
        __syncthreads();
        const float* inT = in + (size_t)tile * TP * F;
#pragma unroll
        for (int k = 0; k < TP * F / 128; ++k) {   // 12 coalesced loads/thread
            int idx = tid + k * 128;               // d = idx & 63 == tid & 63
            us[idx] = (inT[idx] + offd) * SCALE;
        }
        __syncthreads();

        for (int px = 0; px < TP / 3; ++px) {
#pragma unroll
            for (int c = 0; c < 3; ++c) {
                int p = px * 3 + c;
                ull accA = 0ull, accB = 0ull;
#pragma unroll
                for (int j = 0; j < 8; ++j) {
                    float4 u4 = *reinterpret_cast<const float4*>(&us[p * F + 8 * j + 4 * h]);
                    accA = ffma2(wr[c][j][0], pack2(u4.x, u4.y), accA);
                    accB = ffma2(wr[c][j][1], pack2(u4.z, u4.w), accB);
                }
                float a0, a1, c0, c1;
                unpack2(accA, a0, a1);
                unpack2(accB, c0, c1);
                float part = (a0 + a1) + (c0 + c1);
                float tot = part + __shfl_xor_sync(0xffffffffu, part, 1) + bs[c];
                run += fmaxf(tot, 0.0f);
                if (h == 0) out[(size_t)(tile * TP + p) * F + e] = run;
            }
        }
    }
    if (h == 0) g_csum[(batch * NCHUNK + chunk) * F + e] = run;
}

// ---------------------------------------------------------------------------
// Final dense 64 -> 8 logits. 192 threads = 24 positions x 8 outputs.
// ---------------------------------------------------------------------------
__global__ __launch_bounds__(192)
void final_kernel(const float* __restrict__ Wf,   // [3][64][8]
                  const float* __restrict__ bf,   // [3][8]
                  float* __restrict__ outp) {
    int batch = blockIdx.x / NCHUNK;
    int chunk = blockIdx.x % NCHUNK;
    int tid = threadIdx.x;
    int ps = tid >> 3;           // 0..23 (position in tile; channel = ps % 3)
    int k  = tid & 7;            // output logit
    int c  = ps % 3;

    size_t base = (size_t)batch * NPOS + (size_t)chunk * CS;
    const float* in = g_bufB + base * F;

    float wreg[64];
#pragma unroll
    for (int e = 0; e < 64; ++e) wreg[e] = Wf[(c * 64 + e) * 8 + k];
    float bv = bf[c * 8 + k];

    float offd = g_off[(batch * NCHUNK + chunk) * F + (tid & 63)];

    __shared__ float us[FT * 68];   // pad 68 for conflict-free LDS.128

    for (int tile = 0; tile < CS / FT; ++tile) {
        __syncthreads();
        const float* inT = in + (size_t)tile * FT * F;
#pragma unroll
        for (int q = 0; q < FT * F / 192; ++q) {   // 8 loads/thread
            int idx = tid + q * 192;               // d = idx & 63 == tid & 63
            int p = idx >> 6, d = idx & 63;
            us[p * 68 + d] = (inT[idx] + offd) * SCALE;
        }
        __syncthreads();

        float acc = bv;
#pragma unroll
        for (int j = 0; j < 16; ++j) {
            float4 u4 = *reinterpret_cast<const float4*>(&us[ps * 68 + 4 * j]);
            acc = fmaf(u4.x, wreg[4 * j    ], acc);
            acc = fmaf(u4.y, wreg[4 * j + 1], acc);
            acc = fmaf(u4.z, wreg[4 * j + 2], acc);
            acc = fmaf(u4.w, wreg[4 * j + 3], acc);
        }
        outp[(base + (size_t)(tile * FT + ps)) * 8 + k] = acc;
    }
}

// ---------------------------------------------------------------------------
// Launch: L0 -> scan -> (L1 -> scan) x3 -> final.  Graph-capturable: launches
// only, no allocs/syncs.  Ping-pong: L1 A->B, L2 B->A, L3 A->B, final reads B.
// ---------------------------------------------------------------------------
extern "C" void kernel_launch(void* const* d_in, const int* in_sizes, int n_in,
                              void* d_out, int out_size) {
    const int*   ex = (const int*)  d_in[0];
    const float* W0 = (const float*)d_in[1];
    const float* b0 = (const float*)d_in[2];
    const float* Wr = (const float*)d_in[3];   // [3][3][64][64]
    const float* br = (const float*)d_in[4];   // [3][3][64]
    const float* Wf = (const float*)d_in[5];   // [3][64][8]
    const float* bf = (const float*)d_in[6];   // [3][8]
    float* outp = (float*)d_out;

    dim3 grid(BATCH * NCHUNK);

    layer0_kernel<<<grid, 64>>>(ex, W0, b0);
    scan_kernel<<<BATCH, 64>>>();

    layer_kernel<<<grid, 128>>>(0, Wr + 0 * 3 * 64 * 64, br + 0 * 3 * 64);
    scan_kernel<<<BATCH, 64>>>();

    layer_kernel<<<grid, 128>>>(1, Wr + 1 * 3 * 64 * 64, br + 1 * 3 * 64);
    scan_kernel<<<BATCH, 64>>>();

    layer_kernel<<<grid, 128>>>(0, Wr + 2 * 3 * 64 * 64, br + 2 * 3 * 64);
    scan_kernel<<<BATCH, 64>>>();

    final_kernel<<<grid, 192>>>(Wf, bf, outp);
}

// round 11
// speedup vs baseline: 1.0021x; 1.0021x over previous
#include <cuda_runtime.h>

// ---------------------------------------------------------------------------
// Problem constants
// ---------------------------------------------------------------------------
#define BATCH   4
#define NPOS    196608          // 256*256*3 positions per batch
#define F       64              // filters
#define NCHUNK  512             // chunks per batch (scan granularity)
#define CS      384             // positions per chunk (multiple of 3)
#define TP      24              // positions staged in smem per tile (8 pixels)
#define FT      24              // final-kernel tile positions
#define SCALE   (1.0f/196608.0f)

typedef unsigned long long ull;

// ---------------------------------------------------------------------------
// Scratch (device globals: allocation-free per harness rules)
// ---------------------------------------------------------------------------
__device__ float g_bufA[(size_t)BATCH * NPOS * F];   // 201 MB
__device__ float g_bufB[(size_t)BATCH * NPOS * F];   // 201 MB
__device__ float g_csum[BATCH * NCHUNK * F];
__device__ float g_off [BATCH * NCHUNK * F];

// ---------------------------------------------------------------------------
// Packed f32x2 helpers (sm_103a packed FMA pipe)
// ---------------------------------------------------------------------------
__device__ __forceinline__ ull pack2(float a, float b) {
    ull r; asm("mov.b64 %0, {%1,%2};" : "=l"(r) : "f"(a), "f"(b)); return r;
}
__device__ __forceinline__ void unpack2(ull v, float& a, float& b) {
    asm("mov.b64 {%0,%1}, %2;" : "=f"(a), "=f"(b) : "l"(v));
}
__device__ __forceinline__ ull ffma2(ull a, ull b, ull c) {
    ull d; asm("fma.rn.f32x2 %0, %1, %2, %3;" : "=l"(d) : "l"(a), "l"(b), "l"(c));
    return d;
}

// ---------------------------------------------------------------------------
// Layer 0: x -> ReLU(w0[c]*x + b0[c]) -> chunk-local cumsum into g_bufA
// One block per (batch, chunk); 64 threads, thread = feature e.
// ---------------------------------------------------------------------------
__global__ __launch_bounds__(64)
void layer0_kernel(const int* __restrict__ ex,
                   const float* __restrict__ W0,   // [3][1][64]
                   const float* __restrict__ b0) { // [3][64]
    int batch = blockIdx.x / NCHUNK;
    int chunk = blockIdx.x % NCHUNK;
    int e = threadIdx.x;
    size_t base = (size_t)batch * NPOS + (size_t)chunk * CS;

    float w[3], bb[3];
#pragma unroll
    for (int c = 0; c < 3; ++c) { w[c] = W0[c * 64 + e]; bb[c] = b0[c * 64 + e]; }

    __shared__ int xs[96];
    float run = 0.0f;
    float* out = g_bufA + base * F;
    const int* exb = ex + base;

    for (int tile = 0; tile < CS / 96; ++tile) {
        __syncthreads();
        xs[threadIdx.x] = exb[tile * 96 + threadIdx.x];
        if (threadIdx.x < 32) xs[threadIdx.x + 64] = exb[tile * 96 + threadIdx.x + 64];
        __syncthreads();
#pragma unroll
        for (int px = 0; px < 32; ++px) {
#pragma unroll
            for (int c = 0; c < 3; ++c) {
                int p = px * 3 + c;
                float xf = (float)xs[p] * 0.25f - 1.0f;   // /8*2-1
                float v = fmaxf(fmaf(w[c], xf, bb[c]), 0.0f);
                run += v;
                out[(size_t)(tile * 96 + p) * F + e] = run;
            }
        }
    }
    g_csum[(batch * NCHUNK + chunk) * F + e] = run;
}

// ---------------------------------------------------------------------------
// Exclusive scan over chunk sums -> per-chunk offsets. One block per batch.
// ---------------------------------------------------------------------------
__global__ __launch_bounds__(64)
void scan_kernel() {
    int b = blockIdx.x;
    int e = threadIdx.x;
    float run = 0.0f;
#pragma unroll 8
    for (int k = 0; k < NCHUNK; ++k) {
        int i = (b * NCHUNK + k) * F + e;
        float t = g_csum[i];
        g_off[i] = run;
        run += t;
    }
}

// ---------------------------------------------------------------------------
// Mid layers 1..3: u = (in + off)*SCALE ; v = ReLU(W[c]^T u + b[c]) ;
// chunk-local cumsum -> out.   128 threads: thread = (feature e, d-half h).
// W columns live in registers (96 regs); u staged in smem, read as LDS.128;
// partner halves combined with shfl_xor(1).
// ---------------------------------------------------------------------------
__global__ __launch_bounds__(128, 3)
void layer_kernel(int src,
                  const float* __restrict__ W,      // [3][64][64] (c,d,e)
                  const float* __restrict__ bias) { // [3][64]
    int batch = blockIdx.x / NCHUNK;
    int chunk = blockIdx.x % NCHUNK;
    int tid = threadIdx.x;
    int lane = tid & 31, wrp = tid >> 5;
    int e = wrp * 16 + (lane >> 1);
    int h = lane & 1;

    const float* in = src ? g_bufB : g_bufA;
    float*       out = src ? g_bufA : g_bufB;
    size_t base = (size_t)batch * NPOS + (size_t)chunk * CS;
    in  += base * F;
    out += base * F;

    // Register-resident weight columns: d in {8j + 4h + 0..3}
    ull wr[3][8][2];
#pragma unroll
    for (int c = 0; c < 3; ++c)
#pragma unroll
        for (int j = 0; j < 8; ++j) {
            int d0 = 8 * j + 4 * h;
            wr[c][j][0] = pack2(W[(c * 64 + d0    ) * 64 + e], W[(c * 64 + d0 + 1) * 64 + e]);
            wr[c][j][1] = pack2(W[(c * 64 + d0 + 2) * 64 + e], W[(c * 64 + d0 + 3) * 64 + e]);
        }
    float bs[3];
#pragma unroll
    for (int c = 0; c < 3; ++c) bs[c] = bias[c * 64 + e];

    float offd = g_off[(batch * NCHUNK + chunk) * F + (tid & 63)];

    __shared__ float us[TP * F];   // 6 KB
    float run = 0.0f;

    for (int tile = 0; tile < CS / TP; ++tile) {
        __syncthreads();
        const float* inT = in + (size_t)tile * TP * F;
#pragma unroll
        for (int k = 0; k < TP * F / 128; ++k) {   // 12 coalesced loads/thread
            int idx = tid + k * 128;               // d = idx & 63 == tid & 63
            us[idx] = (inT[idx] + offd) * SCALE;
        }
        __syncthreads();

        for (int px = 0; px < TP / 3; ++px) {
#pragma unroll
            for (int c = 0; c < 3; ++c) {
                int p = px * 3 + c;
                ull accA = 0ull, accB = 0ull;
#pragma unroll
                for (int j = 0; j < 8; ++j) {
                    float4 u4 = *reinterpret_cast<const float4*>(&us[p * F + 8 * j + 4 * h]);
                    accA = ffma2(wr[c][j][0], pack2(u4.x, u4.y), accA);
                    accB = ffma2(wr[c][j][1], pack2(u4.z, u4.w), accB);
                }
                float a0, a1, c0, c1;
                unpack2(accA, a0, a1);
                unpack2(accB, c0, c1);
                float part = (a0 + a1) + (c0 + c1);
                float tot = part + __shfl_xor_sync(0xffffffffu, part, 1) + bs[c];
                run += fmaxf(tot, 0.0f);
                if (h == 0) out[(size_t)(tile * TP + p) * F + e] = run;
            }
        }
    }
    if (h == 0) g_csum[(batch * NCHUNK + chunk) * F + e] = run;
}

// ---------------------------------------------------------------------------
// Final dense 64 -> 8 logits. 192 threads = 24 positions x 8 outputs.
// ---------------------------------------------------------------------------
__global__ __launch_bounds__(192)
void final_kernel(const float* __restrict__ Wf,   // [3][64][8]
                  const float* __restrict__ bf,   // [3][8]
                  float* __restrict__ outp) {
    int batch = blockIdx.x / NCHUNK;
    int chunk = blockIdx.x % NCHUNK;
    int tid = threadIdx.x;
    int ps = tid >> 3;           // 0..23 (position in tile; channel = ps % 3)
    int k  = tid & 7;            // output logit
    int c  = ps % 3;

    size_t base = (size_t)batch * NPOS + (size_t)chunk * CS;
    const float* in = g_bufB + base * F;

    float wreg[64];
#pragma unroll
    for (int e = 0; e < 64; ++e) wreg[e] = Wf[(c * 64 + e) * 8 + k];
    float bv = bf[c * 8 + k];

    float offd = g_off[(batch * NCHUNK + chunk) * F + (tid & 63)];

    __shared__ float us[FT * 68];   // pad 68 for conflict-free LDS.128

    for (int tile = 0; tile < CS / FT; ++tile) {
        __syncthreads();
        const float* inT = in + (size_t)tile * FT * F;
#pragma unroll
        for (int q = 0; q < FT * F / 192; ++q) {   // 8 loads/thread
            int idx = tid + q * 192;               // d = idx & 63 == tid & 63
            int p = idx >> 6, d = idx & 63;
            us[p * 68 + d] = (inT[idx] + offd) * SCALE;
        }
        __syncthreads();

        float acc = bv;
#pragma unroll
        for (int j = 0; j < 16; ++j) {
            float4 u4 = *reinterpret_cast<const float4*>(&us[ps * 68 + 4 * j]);
            acc = fmaf(u4.x, wreg[4 * j    ], acc);
            acc = fmaf(u4.y, wreg[4 * j + 1], acc);
            acc = fmaf(u4.z, wreg[4 * j + 2], acc);
            acc = fmaf(u4.w, wreg[4 * j + 3], acc);
        }
        outp[(base + (size_t)(tile * FT + ps)) * 8 + k] = acc;
    }
}

// ---------------------------------------------------------------------------
// Launch: L0 -> scan -> (L1 -> scan) x3 -> final.  Graph-capturable: launches
// only, no allocs/syncs.  Ping-pong: L1 A->B, L2 B->A, L3 A->B, final reads B.
// ---------------------------------------------------------------------------
extern "C" void kernel_launch(void* const* d_in, const int* in_sizes, int n_in,
                              void* d_out, int out_size) {
    const int*   ex = (const int*)  d_in[0];
    const float* W0 = (const float*)d_in[1];
    const float* b0 = (const float*)d_in[2];
    const float* Wr = (const float*)d_in[3];   // [3][3][64][64]
    const float* br = (const float*)d_in[4];   // [3][3][64]
    const float* Wf = (const float*)d_in[5];   // [3][64][8]
    const float* bf = (const float*)d_in[6];   // [3][8]
    float* outp = (float*)d_out;

    dim3 grid(BATCH * NCHUNK);

    layer0_kernel<<<grid, 64>>>(ex, W0, b0);
    scan_kernel<<<BATCH, 64>>>();

    layer_kernel<<<grid, 128>>>(0, Wr + 0 * 3 * 64 * 64, br + 0 * 3 * 64);
    scan_kernel<<<BATCH, 64>>>();

    layer_kernel<<<grid, 128>>>(1, Wr + 1 * 3 * 64 * 64, br + 1 * 3 * 64);
    scan_kernel<<<BATCH, 64>>>();

    layer_kernel<<<grid, 128>>>(0, Wr + 2 * 3 * 64 * 64, br + 2 * 3 * 64);
    scan_kernel<<<BATCH, 64>>>();

    final_kernel<<<grid, 192>>>(Wf, bf, outp);
}

// round 12
// speedup vs baseline: 1.4654x; 1.4624x over previous
#include <cuda_runtime.h>

// ---------------------------------------------------------------------------
// Problem constants
// ---------------------------------------------------------------------------
#define BATCH   4
#define NPOS    196608          // 256*256*3 positions per batch
#define F       64              // filters
#define NCHUNK  512             // chunks per batch (scan granularity)
#define CS      384             // positions per chunk (multiple of 3)
#define TP      24              // positions staged in smem per tile (8 pixels)
#define FT      24              // final-kernel tile positions
#define SCALE   (1.0f/196608.0f)

typedef unsigned long long ull;

// ---------------------------------------------------------------------------
// Scratch (device globals: allocation-free per harness rules)
// ---------------------------------------------------------------------------
__device__ float g_bufA[(size_t)BATCH * NPOS * F];   // 201 MB
__device__ float g_bufB[(size_t)BATCH * NPOS * F];   // 201 MB
__device__ float g_csum[BATCH * NCHUNK * F];
__device__ float g_off [BATCH * NCHUNK * F];

// ---------------------------------------------------------------------------
// Packed f32x2 helpers (sm_103a packed FMA pipe)
// ---------------------------------------------------------------------------
__device__ __forceinline__ ull pack2(float a, float b) {
    ull r; asm("mov.b64 %0, {%1,%2};" : "=l"(r) : "f"(a), "f"(b)); return r;
}
__device__ __forceinline__ void unpack2(ull v, float& a, float& b) {
    asm("mov.b64 {%0,%1}, %2;" : "=f"(a), "=f"(b) : "l"(v));
}
__device__ __forceinline__ ull ffma2(ull a, ull b, ull c) {
    ull d; asm("fma.rn.f32x2 %0, %1, %2, %3;" : "=l"(d) : "l"(a), "l"(b), "l"(c));
    return d;
}

// ---------------------------------------------------------------------------
// Layer 0: x -> ReLU(w0[c]*x + b0[c]) -> chunk-local cumsum into g_bufA
// One block per (batch, chunk); 64 threads, thread = feature e.
// ---------------------------------------------------------------------------
__global__ __launch_bounds__(64)
void layer0_kernel(const int* __restrict__ ex,
                   const float* __restrict__ W0,   // [3][1][64]
                   const float* __restrict__ b0) { // [3][64]
    int batch = blockIdx.x / NCHUNK;
    int chunk = blockIdx.x % NCHUNK;
    int e = threadIdx.x;
    size_t base = (size_t)batch * NPOS + (size_t)chunk * CS;

    float w[3], bb[3];
#pragma unroll
    for (int c = 0; c < 3; ++c) { w[c] = W0[c * 64 + e]; bb[c] = b0[c * 64 + e]; }

    __shared__ int xs[96];
    float run = 0.0f;
    float* out = g_bufA + base * F;
    const int* exb = ex + base;

    for (int tile = 0; tile < CS / 96; ++tile) {
        __syncthreads();
        xs[threadIdx.x] = exb[tile * 96 + threadIdx.x];
        if (threadIdx.x < 32) xs[threadIdx.x + 64] = exb[tile * 96 + threadIdx.x + 64];
        __syncthreads();
#pragma unroll
        for (int px = 0; px < 32; ++px) {
#pragma unroll
            for (int c = 0; c < 3; ++c) {
                int p = px * 3 + c;
                float xf = (float)xs[p] * 0.25f - 1.0f;   // /8*2-1
                float v = fmaxf(fmaf(w[c], xf, bb[c]), 0.0f);
                run += v;
                out[(size_t)(tile * 96 + p) * F + e] = run;
            }
        }
    }
    g_csum[(batch * NCHUNK + chunk) * F + e] = run;
}

// ---------------------------------------------------------------------------
// Parallel exclusive scan over chunk sums -> per-chunk offsets.
// grid = (BATCH, F), block = 512 threads (one per chunk).
// Warp-shuffle inclusive scan + 16-warp smem combine.
// ---------------------------------------------------------------------------
__global__ __launch_bounds__(512)
void scan_kernel() {
    int b = blockIdx.x;
    int e = blockIdx.y;
    int t = threadIdx.x;            // chunk index 0..511
    int lane = t & 31, w = t >> 5;  // 16 warps

    int i = (b * NCHUNK + t) * F + e;
    float v = g_csum[i];

    // inclusive warp scan
    float s = v;
#pragma unroll
    for (int d = 1; d < 32; d <<= 1) {
        float n = __shfl_up_sync(0xffffffffu, s, d);
        if (lane >= d) s += n;
    }

    __shared__ float ws[16];
    if (lane == 31) ws[w] = s;
    __syncthreads();
    if (t < 16) {
        float x = ws[t];
#pragma unroll
        for (int d = 1; d < 16; d <<= 1) {
            float n = __shfl_up_sync(0x0000ffffu, x, d);
            if (t >= d) x += n;
        }
        ws[t] = x;
    }
    __syncthreads();

    float warp_pre = (w > 0) ? ws[w - 1] : 0.0f;
    g_off[i] = warp_pre + (s - v);   // exclusive prefix
}

// ---------------------------------------------------------------------------
// Mid layers 1..3: u = (in + off)*SCALE ; v = ReLU(W[c]^T u + b[c]) ;
// chunk-local cumsum -> out.   128 threads: thread = (feature e, d-half h).
// W columns live in registers (96 regs); u staged in smem, read as LDS.128;
// partner halves combined with shfl_xor(1).
// ---------------------------------------------------------------------------
__global__ __launch_bounds__(128, 3)
void layer_kernel(int src,
                  const float* __restrict__ W,      // [3][64][64] (c,d,e)
                  const float* __restrict__ bias) { // [3][64]
    int batch = blockIdx.x / NCHUNK;
    int chunk = blockIdx.x % NCHUNK;
    int tid = threadIdx.x;
    int lane = tid & 31, wrp = tid >> 5;
    int e = wrp * 16 + (lane >> 1);
    int h = lane & 1;

    const float* in = src ? g_bufB : g_bufA;
    float*       out = src ? g_bufA : g_bufB;
    size_t base = (size_t)batch * NPOS + (size_t)chunk * CS;
    in  += base * F;
    out += base * F;

    // Register-resident weight columns: d in {8j + 4h + 0..3}
    ull wr[3][8][2];
#pragma unroll
    for (int c = 0; c < 3; ++c)
#pragma unroll
        for (int j = 0; j < 8; ++j) {
            int d0 = 8 * j + 4 * h;
            wr[c][j][0] = pack2(W[(c * 64 + d0    ) * 64 + e], W[(c * 64 + d0 + 1) * 64 + e]);
            wr[c][j][1] = pack2(W[(c * 64 + d0 + 2) * 64 + e], W[(c * 64 + d0 + 3) * 64 + e]);
        }
    float bs[3];
#pragma unroll
    for (int c = 0; c < 3; ++c) bs[c] = bias[c * 64 + e];

    float offd = g_off[(batch * NCHUNK + chunk) * F + (tid & 63)];

    __shared__ float us[TP * F];   // 6 KB
    float run = 0.0f;

    for (int tile = 0; tile < CS / TP; ++tile) {
        __syncthreads();
        const float* inT = in + (size_t)tile * TP * F;
#pragma unroll
        for (int k = 0; k < TP * F / 128; ++k) {   // 12 coalesced loads/thread
            int idx = tid + k * 128;               // d = idx & 63 == tid & 63
            us[idx] = (inT[idx] + offd) * SCALE;
        }
        __syncthreads();

        for (int px = 0; px < TP / 3; ++px) {
#pragma unroll
            for (int c = 0; c < 3; ++c) {
                int p = px * 3 + c;
                ull accA = 0ull, accB = 0ull;
#pragma unroll
                for (int j = 0; j < 8; ++j) {
                    float4 u4 = *reinterpret_cast<const float4*>(&us[p * F + 8 * j + 4 * h]);
                    accA = ffma2(wr[c][j][0], pack2(u4.x, u4.y), accA);
                    accB = ffma2(wr[c][j][1], pack2(u4.z, u4.w), accB);
                }
                float a0, a1, c0, c1;
                unpack2(accA, a0, a1);
                unpack2(accB, c0, c1);
                float part = (a0 + a1) + (c0 + c1);
                float tot = part + __shfl_xor_sync(0xffffffffu, part, 1) + bs[c];
                run += fmaxf(tot, 0.0f);
                if (h == 0) out[(size_t)(tile * TP + p) * F + e] = run;
            }
        }
    }
    if (h == 0) g_csum[(batch * NCHUNK + chunk) * F + e] = run;
}

// ---------------------------------------------------------------------------
// Final dense 64 -> 8 logits. 192 threads = 24 positions x 8 outputs.
// ---------------------------------------------------------------------------
__global__ __launch_bounds__(192)
void final_kernel(const float* __restrict__ Wf,   // [3][64][8]
                  const float* __restrict__ bf,   // [3][8]
                  float* __restrict__ outp) {
    int batch = blockIdx.x / NCHUNK;
    int chunk = blockIdx.x % NCHUNK;
    int tid = threadIdx.x;
    int ps = tid >> 3;           // 0..23 (position in tile; channel = ps % 3)
    int k  = tid & 7;            // output logit
    int c  = ps % 3;

    size_t base = (size_t)batch * NPOS + (size_t)chunk * CS;
    const float* in = g_bufB + base * F;

    float wreg[64];
#pragma unroll
    for (int e = 0; e < 64; ++e) wreg[e] = Wf[(c * 64 + e) * 8 + k];
    float bv = bf[c * 8 + k];

    float offd = g_off[(batch * NCHUNK + chunk) * F + (tid & 63)];

    __shared__ float us[FT * 68];   // pad 68 for conflict-free LDS.128

    for (int tile = 0; tile < CS / FT; ++tile) {
        __syncthreads();
        const float* inT = in + (size_t)tile * FT * F;
#pragma unroll
        for (int q = 0; q < FT * F / 192; ++q) {   // 8 loads/thread
            int idx = tid + q * 192;               // d = idx & 63 == tid & 63
            int p = idx >> 6, d = idx & 63;
            us[p * 68 + d] = (inT[idx] + offd) * SCALE;
        }
        __syncthreads();

        float acc = bv;
#pragma unroll
        for (int j = 0; j < 16; ++j) {
            float4 u4 = *reinterpret_cast<const float4*>(&us[ps * 68 + 4 * j]);
            acc = fmaf(u4.x, wreg[4 * j    ], acc);
            acc = fmaf(u4.y, wreg[4 * j + 1], acc);
            acc = fmaf(u4.z, wreg[4 * j + 2], acc);
            acc = fmaf(u4.w, wreg[4 * j + 3], acc);
        }
        outp[(base + (size_t)(tile * FT + ps)) * 8 + k] = acc;
    }
}

// ---------------------------------------------------------------------------
// Launch: L0 -> scan -> (L1 -> scan) x3 -> final.  Graph-capturable: launches
// only, no allocs/syncs.  Ping-pong: L1 A->B, L2 B->A, L3 A->B, final reads B.
// ---------------------------------------------------------------------------
extern "C" void kernel_launch(void* const* d_in, const int* in_sizes, int n_in,
                              void* d_out, int out_size) {
    const int*   ex = (const int*)  d_in[0];
    const float* W0 = (const float*)d_in[1];
    const float* b0 = (const float*)d_in[2];
    const float* Wr = (const float*)d_in[3];   // [3][3][64][64]
    const float* br = (const float*)d_in[4];   // [3][3][64]
    const float* Wf = (const float*)d_in[5];   // [3][64][8]
    const float* bf = (const float*)d_in[6];   // [3][8]
    float* outp = (float*)d_out;

    dim3 grid(BATCH * NCHUNK);
    dim3 sgrid(BATCH, F);

    layer0_kernel<<<grid, 64>>>(ex, W0, b0);
    scan_kernel<<<sgrid, 512>>>();

    layer_kernel<<<grid, 128>>>(0, Wr + 0 * 3 * 64 * 64, br + 0 * 3 * 64);
    scan_kernel<<<sgrid, 512>>>();

    layer_kernel<<<grid, 128>>>(1, Wr + 1 * 3 * 64 * 64, br + 1 * 3 * 64);
    scan_kernel<<<sgrid, 512>>>();

    layer_kernel<<<grid, 128>>>(0, Wr + 2 * 3 * 64 * 64, br + 2 * 3 * 64);
    scan_kernel<<<sgrid, 512>>>();

    final_kernel<<<grid, 192>>>(Wf, bf, outp);
}